// round 8
// baseline (speedup 1.0000x reference)
#include <cuda_runtime.h>
#include <cuda_fp16.h>
#include <cstdint>

#define EMB   64
#define NMAX  300000
#define EMAX  4200000
#define TB    256

// ---------------- scratch (__device__ globals; allocation-free rule) --------
__device__ int   g_deg  [NMAX];
__device__ float g_dinv [NMAX];
__device__ int   g_loc  [NMAX];
__device__ int   g_bsum [2048];
__device__ int   g_bbase[2048];
__device__ int2  g_rng  [NMAX];               // {row_start, cursor/row_end}
__device__ __align__(16) int2 g_adj[EMAX];    // {col, bits(dinv[col])}
__device__ uint2 g_h0[(size_t)NMAX * 16];     // x0 fp16 (4 halves per uint2)
__device__ uint2 g_h1[(size_t)NMAX * 16];     // x1 fp16
__device__ uint2 g_h2[(size_t)NMAX * 16];     // x2 fp16

// ---------------------------------------------------------------------------
__device__ __forceinline__ float4 h4_to_f4(uint2 h) {
    __half2 a = *(__half2*)&h.x;
    __half2 b = *(__half2*)&h.y;
    float2 fa = __half22float2(a), fb = __half22float2(b);
    return make_float4(fa.x, fa.y, fb.x, fb.y);
}
__device__ __forceinline__ uint2 f4_to_h4(float4 v) {
    __half2 a = __floats2half2_rn(v.x, v.y);
    __half2 b = __floats2half2_rn(v.z, v.w);
    uint2 r;
    r.x = *(unsigned*)&a;
    r.y = *(unsigned*)&b;
    return r;
}

// ---------------------------------------------------------------------------
__global__ void k_zero_deg(int n) {
    int i = blockIdx.x * blockDim.x + threadIdx.x;
    if (i < n) g_deg[i] = 0;
}

__global__ void k_count_sym(const int* __restrict__ row,
                            const int* __restrict__ col, int Eh) {
    int i = blockIdx.x * blockDim.x + threadIdx.x;
    if (i >= Eh) return;
    atomicAdd(&g_deg[row[i]], 1);
    atomicAdd(&g_deg[col[i]], 1);
}

__global__ void k_scan_local(int n) {
    __shared__ int sh[TB];
    int i = blockIdx.x * TB + threadIdx.x;
    int v = (i < n) ? g_deg[i] : 0;
    sh[threadIdx.x] = v; __syncthreads();
    #pragma unroll
    for (int ofs = 1; ofs < TB; ofs <<= 1) {
        int t = (threadIdx.x >= ofs) ? sh[threadIdx.x - ofs] : 0;
        __syncthreads();
        sh[threadIdx.x] += t;
        __syncthreads();
    }
    if (i < n) g_loc[i] = sh[threadIdx.x] - v;
    if (threadIdx.x == TB - 1) g_bsum[blockIdx.x] = sh[TB - 1];
}

__global__ void k_scan_bsum(int nb) {
    __shared__ int sh[1024];
    int tid = threadIdx.x;
    int c0 = tid * 2, c1 = tid * 2 + 1;
    int a = (c0 < nb) ? g_bsum[c0] : 0;
    int b = (c1 < nb) ? g_bsum[c1] : 0;
    int tot = a + b;
    sh[tid] = tot; __syncthreads();
    #pragma unroll
    for (int ofs = 1; ofs < 1024; ofs <<= 1) {
        int t = (tid >= ofs) ? sh[tid - ofs] : 0;
        __syncthreads();
        sh[tid] += t;
        __syncthreads();
    }
    int base = sh[tid] - tot;
    if (c0 < nb) g_bbase[c0] = base;
    if (c1 < nb) g_bbase[c1] = base + a;
}

__global__ void k_scan_add(int n) {
    int i = blockIdx.x * TB + threadIdx.x;
    if (i >= n) return;
    int o = g_loc[i] + g_bbase[blockIdx.x];
    g_rng[i] = make_int2(o, o);
    g_dinv[i] = rsqrtf((float)(g_deg[i] + 1));   // +1 self loop
}

__global__ void k_fill_sym(const int* __restrict__ row,
                           const int* __restrict__ col, int Eh) {
    int i = blockIdx.x * blockDim.x + threadIdx.x;
    if (i >= Eh) return;
    int u = row[i];
    int v = col[i];
    float du = __ldg(&g_dinv[u]);
    float dv = __ldg(&g_dinv[v]);
    int pu = atomicAdd(&g_rng[u].y, 1);
    g_adj[pu] = make_int2(v, __float_as_int(dv));
    int pv = atomicAdd(&g_rng[v].y, 1);
    g_adj[pv] = make_int2(u, __float_as_int(du));
}

// emb (fp32) -> x0 (fp16)
__global__ void k_prep(const float* __restrict__ ue,
                       const float* __restrict__ ie,
                       int U, int N) {
    int i = blockIdx.x * blockDim.x + threadIdx.x;
    int total = N * 16;
    if (i >= total) return;
    int node = i >> 4;
    int c = i & 15;
    const float4* p = (node < U)
        ? (const float4*)ue + (size_t)node * 16
        : (const float4*)ie + (size_t)(node - U) * 16;
    g_h0[i] = f4_to_h4(__ldg(p + c));
}

// ---------------------------------------------------------------------------
// Fused layer: 16 threads per node (half-warp), thread c owns halves [4c,4c+4).
template<bool LAST>
__global__ void __launch_bounds__(TB)
k_layer(const uint2* __restrict__ x,
        uint2* __restrict__ xn,
        const float* __restrict__ ue,
        const float* __restrict__ ie,
        int U,
        float* __restrict__ acc,
        int N) {
    int t = blockIdx.x * blockDim.x + threadIdx.x;
    int node = t >> 4;
    if (node >= N) return;
    int c = t & 15;

    float d = __ldg(&g_dinv[node]);
    int2 rng = __ldg(&g_rng[node]);
    int e = rng.x, end = rng.y;

    size_t idx = (size_t)node * 16 + c;
    float4 xs = h4_to_f4(__ldg(x + idx));
    float sw = d * d;
    float4 s0 = make_float4(sw * xs.x, sw * xs.y, sw * xs.z, sw * xs.w);
    float4 s1 = make_float4(0.f, 0.f, 0.f, 0.f);

    // peel one edge so e is even -> 16B-aligned uint4 adjacency loads
    if ((e & 1) && e < end) {
        int2 a0 = __ldg(&g_adj[e]);
        float4 v0 = h4_to_f4(__ldg(x + (size_t)a0.x * 16 + c));
        float w0 = d * __int_as_float(a0.y);
        s0.x += w0 * v0.x; s0.y += w0 * v0.y; s0.z += w0 * v0.z; s0.w += w0 * v0.w;
        ++e;
    }

    // 8-wide unroll: 4 uint4 adj loads (2 edges each) + 8 row gathers in flight
    while (e + 8 <= end) {
        const uint4* ap = (const uint4*)&g_adj[e];
        uint4 q0 = __ldg(ap);
        uint4 q1 = __ldg(ap + 1);
        uint4 q2 = __ldg(ap + 2);
        uint4 q3 = __ldg(ap + 3);
        float4 v0 = h4_to_f4(__ldg(x + (size_t)q0.x * 16 + c));
        float4 v1 = h4_to_f4(__ldg(x + (size_t)q0.z * 16 + c));
        float4 v2 = h4_to_f4(__ldg(x + (size_t)q1.x * 16 + c));
        float4 v3 = h4_to_f4(__ldg(x + (size_t)q1.z * 16 + c));
        float4 v4 = h4_to_f4(__ldg(x + (size_t)q2.x * 16 + c));
        float4 v5 = h4_to_f4(__ldg(x + (size_t)q2.z * 16 + c));
        float4 v6 = h4_to_f4(__ldg(x + (size_t)q3.x * 16 + c));
        float4 v7 = h4_to_f4(__ldg(x + (size_t)q3.z * 16 + c));
        float w0 = d * __uint_as_float(q0.y);
        float w1 = d * __uint_as_float(q0.w);
        float w2 = d * __uint_as_float(q1.y);
        float w3 = d * __uint_as_float(q1.w);
        float w4 = d * __uint_as_float(q2.y);
        float w5 = d * __uint_as_float(q2.w);
        float w6 = d * __uint_as_float(q3.y);
        float w7 = d * __uint_as_float(q3.w);
        s0.x += w0 * v0.x + w2 * v2.x + w4 * v4.x + w6 * v6.x;
        s1.x += w1 * v1.x + w3 * v3.x + w5 * v5.x + w7 * v7.x;
        s0.y += w0 * v0.y + w2 * v2.y + w4 * v4.y + w6 * v6.y;
        s1.y += w1 * v1.y + w3 * v3.y + w5 * v5.y + w7 * v7.y;
        s0.z += w0 * v0.z + w2 * v2.z + w4 * v4.z + w6 * v6.z;
        s1.z += w1 * v1.z + w3 * v3.z + w5 * v5.z + w7 * v7.z;
        s0.w += w0 * v0.w + w2 * v2.w + w4 * v4.w + w6 * v6.w;
        s1.w += w1 * v1.w + w3 * v3.w + w5 * v5.w + w7 * v7.w;
        e += 8;
    }
    while (e + 2 <= end) {
        const uint4* ap = (const uint4*)&g_adj[e];
        uint4 q0 = __ldg(ap);
        float4 v0 = h4_to_f4(__ldg(x + (size_t)q0.x * 16 + c));
        float4 v1 = h4_to_f4(__ldg(x + (size_t)q0.z * 16 + c));
        float w0 = d * __uint_as_float(q0.y);
        float w1 = d * __uint_as_float(q0.w);
        s0.x += w0 * v0.x; s0.y += w0 * v0.y; s0.z += w0 * v0.z; s0.w += w0 * v0.w;
        s1.x += w1 * v1.x; s1.y += w1 * v1.y; s1.z += w1 * v1.z; s1.w += w1 * v1.w;
        e += 2;
    }
    if (e < end) {
        int2 a0 = __ldg(&g_adj[e]);
        float4 v0 = h4_to_f4(__ldg(x + (size_t)a0.x * 16 + c));
        float w0 = d * __int_as_float(a0.y);
        s0.x += w0 * v0.x; s0.y += w0 * v0.y; s0.z += w0 * v0.z; s0.w += w0 * v0.w;
    }
    float4 s = make_float4(s0.x + s1.x, s0.y + s1.y, s0.z + s1.z, s0.w + s1.w);

    if (!LAST) {
        xn[idx] = f4_to_h4(s);
    } else {
        const float4* pe = (node < U)
            ? (const float4*)ue + (size_t)node * 16
            : (const float4*)ie + (size_t)(node - U) * 16;
        float4 a  = __ldg(pe + c);
        float4 v1 = h4_to_f4(__ldg(&g_h1[idx]));
        a.x += v1.x + xs.x + s.x;
        a.y += v1.y + xs.y + s.y;
        a.z += v1.z + xs.z + s.z;
        a.w += v1.w + xs.w + s.w;
        ((float4*)acc)[idx] = a;
    }
}

// ---------------------------------------------------------------------------
extern "C" void kernel_launch(void* const* d_in, const int* in_sizes, int n_in,
                              void* d_out, int out_size) {
    const int*   edge = (const int*)d_in[0];
    const float* uemb = (const float*)d_in[1];
    const float* iemb = (const float*)d_in[2];

    int E = in_sizes[0] / 2;       // total directed edges
    int Eh = E / 2;                // unique interactions (mirrored halves)
    int U = in_sizes[1] / EMB;
    int I = in_sizes[2] / EMB;
    int N = U + I;

    const int* row = edge;
    const int* col = edge + E;
    float* acc = (float*)d_out;

    uint2* h0; cudaGetSymbolAddress((void**)&h0, g_h0);
    uint2* h1; cudaGetSymbolAddress((void**)&h1, g_h1);
    uint2* h2; cudaGetSymbolAddress((void**)&h2, g_h2);

    int NB = (N + TB - 1) / TB;
    int EBh = (Eh + TB - 1) / TB;

    k_zero_deg  <<<NB, TB>>>(N);
    k_count_sym <<<EBh, TB>>>(row, col, Eh);
    k_scan_local<<<NB, TB>>>(N);
    k_scan_bsum <<<1, 1024>>>(NB);
    k_scan_add  <<<NB, TB>>>(N);
    k_fill_sym  <<<EBh, TB>>>(row, col, Eh);

    int pblocks = (N * 16 + TB - 1) / TB;
    k_prep<<<pblocks, TB>>>(uemb, iemb, U, N);

    int lblocks = (N * 16 + TB - 1) / TB;        // half-warp per node
    k_layer<false><<<lblocks, TB>>>(h0, h1, uemb, iemb, U, acc, N);
    k_layer<false><<<lblocks, TB>>>(h1, h2, uemb, iemb, U, acc, N);
    k_layer<true ><<<lblocks, TB>>>(h2, nullptr, uemb, iemb, U, acc, N);
}

// round 9
// speedup vs baseline: 1.0401x; 1.0401x over previous
#include <cuda_runtime.h>
#include <cuda_fp16.h>
#include <cstdint>

#define EMB   64
#define NMAX  300000
#define EMAX  5100000
#define TB    256

// ---------------- scratch (__device__ globals; allocation-free rule) --------
__device__ int   g_deg  [NMAX];
__device__ float g_dinv [NMAX];
__device__ int   g_loc  [NMAX];
__device__ int   g_bsum [2048];
__device__ int   g_bbase[2048];
__device__ int2  g_rng  [NMAX];               // {row_start, cursor/row_end}
__device__ __align__(16) int2 g_adj[EMAX];    // {col, bits(dinv[col])}
__device__ uint2 g_h0[(size_t)NMAX * 16];     // x0 fp16 (4 halves per uint2)
__device__ uint2 g_h1[(size_t)NMAX * 16];     // x1 fp16
__device__ uint2 g_h2[(size_t)NMAX * 16];     // x2 fp16

// ---------------------------------------------------------------------------
__device__ __forceinline__ float4 h4_to_f4(uint2 h) {
    __half2 a = *(__half2*)&h.x;
    __half2 b = *(__half2*)&h.y;
    float2 fa = __half22float2(a), fb = __half22float2(b);
    return make_float4(fa.x, fa.y, fb.x, fb.y);
}
__device__ __forceinline__ uint2 f4_to_h4(float4 v) {
    __half2 a = __floats2half2_rn(v.x, v.y);
    __half2 b = __floats2half2_rn(v.z, v.w);
    uint2 r;
    r.x = *(unsigned*)&a;
    r.y = *(unsigned*)&b;
    return r;
}

// ---------------------------------------------------------------------------
__global__ void k_zero_deg(int n) {
    int i = blockIdx.x * blockDim.x + threadIdx.x;
    if (i < n) g_deg[i] = 0;
}

__global__ void k_count_sym(const int* __restrict__ row,
                            const int* __restrict__ col, int Eh) {
    int i = blockIdx.x * blockDim.x + threadIdx.x;
    if (i >= Eh) return;
    atomicAdd(&g_deg[row[i]], 1);
    atomicAdd(&g_deg[col[i]], 1);
}

// scan over PADDED degrees: pdeg = (deg+3) & ~3
__global__ void k_scan_local(int n) {
    __shared__ int sh[TB];
    int i = blockIdx.x * TB + threadIdx.x;
    int v = 0;
    if (i < n) v = (g_deg[i] + 3) & ~3;
    sh[threadIdx.x] = v; __syncthreads();
    #pragma unroll
    for (int ofs = 1; ofs < TB; ofs <<= 1) {
        int t = (threadIdx.x >= ofs) ? sh[threadIdx.x - ofs] : 0;
        __syncthreads();
        sh[threadIdx.x] += t;
        __syncthreads();
    }
    if (i < n) g_loc[i] = sh[threadIdx.x] - v;
    if (threadIdx.x == TB - 1) g_bsum[blockIdx.x] = sh[TB - 1];
}

__global__ void k_scan_bsum(int nb) {
    __shared__ int sh[1024];
    int tid = threadIdx.x;
    int c0 = tid * 2, c1 = tid * 2 + 1;
    int a = (c0 < nb) ? g_bsum[c0] : 0;
    int b = (c1 < nb) ? g_bsum[c1] : 0;
    int tot = a + b;
    sh[tid] = tot; __syncthreads();
    #pragma unroll
    for (int ofs = 1; ofs < 1024; ofs <<= 1) {
        int t = (tid >= ofs) ? sh[tid - ofs] : 0;
        __syncthreads();
        sh[tid] += t;
        __syncthreads();
    }
    int base = sh[tid] - tot;
    if (c0 < nb) g_bbase[c0] = base;
    if (c1 < nb) g_bbase[c1] = base + a;
}

__global__ void k_scan_add(int n) {
    int i = blockIdx.x * TB + threadIdx.x;
    if (i >= n) return;
    int o = g_loc[i] + g_bbase[blockIdx.x];
    g_rng[i] = make_int2(o, o);
    g_dinv[i] = rsqrtf((float)(g_deg[i] + 1));   // +1 self loop
}

__global__ void k_fill_sym(const int* __restrict__ row,
                           const int* __restrict__ col, int Eh) {
    int i = blockIdx.x * blockDim.x + threadIdx.x;
    if (i >= Eh) return;
    int u = row[i];
    int v = col[i];
    float du = __ldg(&g_dinv[u]);
    float dv = __ldg(&g_dinv[v]);
    int pu = atomicAdd(&g_rng[u].y, 1);
    g_adj[pu] = make_int2(v, __float_as_int(dv));
    int pv = atomicAdd(&g_rng[v].y, 1);
    g_adj[pv] = make_int2(u, __float_as_int(du));
}

// write zero-weight sentinels into the <=3 pad slots per row
__global__ void k_pad(int n) {
    int i = blockIdx.x * blockDim.x + threadIdx.x;
    if (i >= n) return;
    int2 rng = g_rng[i];
    int pend = rng.x + ((rng.y - rng.x + 3) & ~3);
    for (int e = rng.y; e < pend; e++)
        g_adj[e] = make_int2(0, 0);          // col 0, weight 0.0f
}

// emb (fp32) -> x0 (fp16)
__global__ void k_prep(const float* __restrict__ ue,
                       const float* __restrict__ ie,
                       int U, int N) {
    int i = blockIdx.x * blockDim.x + threadIdx.x;
    int total = N * 16;
    if (i >= total) return;
    int node = i >> 4;
    int c = i & 15;
    const float4* p = (node < U)
        ? (const float4*)ue + (size_t)node * 16
        : (const float4*)ie + (size_t)(node - U) * 16;
    g_h0[i] = f4_to_h4(__ldg(p + c));
}

// ---------------------------------------------------------------------------
// Fused layer: 16 threads per node (half-warp), thread c owns halves [4c,4c+4).
// Rows padded to multiple of 4 -> single branch-free 4-wide loop.
template<bool LAST>
__global__ void __launch_bounds__(TB)
k_layer(const uint2* __restrict__ x,
        uint2* __restrict__ xn,
        const float* __restrict__ ue,
        const float* __restrict__ ie,
        int U,
        float* __restrict__ acc,
        int N) {
    int t = blockIdx.x * blockDim.x + threadIdx.x;
    int node = t >> 4;
    if (node >= N) return;
    int c = t & 15;

    float d = __ldg(&g_dinv[node]);
    int2 rng = __ldg(&g_rng[node]);
    int e = rng.x;
    int pend = e + ((rng.y - e + 3) & ~3);

    size_t idx = (size_t)node * 16 + c;
    float4 xs = h4_to_f4(__ldg(x + idx));
    float sw = d * d;
    float4 s0 = make_float4(sw * xs.x, sw * xs.y, sw * xs.z, sw * xs.w);
    float4 s1 = make_float4(0.f, 0.f, 0.f, 0.f);

    // branch-free 4-wide loop over padded row
    while (e < pend) {
        int2 a0 = __ldg(&g_adj[e]);
        int2 a1 = __ldg(&g_adj[e + 1]);
        int2 a2 = __ldg(&g_adj[e + 2]);
        int2 a3 = __ldg(&g_adj[e + 3]);
        float4 v0 = h4_to_f4(__ldg(x + (size_t)a0.x * 16 + c));
        float4 v1 = h4_to_f4(__ldg(x + (size_t)a1.x * 16 + c));
        float4 v2 = h4_to_f4(__ldg(x + (size_t)a2.x * 16 + c));
        float4 v3 = h4_to_f4(__ldg(x + (size_t)a3.x * 16 + c));
        float w0 = d * __int_as_float(a0.y);
        float w1 = d * __int_as_float(a1.y);
        float w2 = d * __int_as_float(a2.y);
        float w3 = d * __int_as_float(a3.y);
        s0.x += w0 * v0.x + w2 * v2.x;  s1.x += w1 * v1.x + w3 * v3.x;
        s0.y += w0 * v0.y + w2 * v2.y;  s1.y += w1 * v1.y + w3 * v3.y;
        s0.z += w0 * v0.z + w2 * v2.z;  s1.z += w1 * v1.z + w3 * v3.z;
        s0.w += w0 * v0.w + w2 * v2.w;  s1.w += w1 * v1.w + w3 * v3.w;
        e += 4;
    }
    float4 s = make_float4(s0.x + s1.x, s0.y + s1.y, s0.z + s1.z, s0.w + s1.w);

    if (!LAST) {
        xn[idx] = f4_to_h4(s);
    } else {
        const float4* pe = (node < U)
            ? (const float4*)ue + (size_t)node * 16
            : (const float4*)ie + (size_t)(node - U) * 16;
        float4 a  = __ldg(pe + c);
        float4 v1 = h4_to_f4(__ldg(&g_h1[idx]));
        a.x += v1.x + xs.x + s.x;
        a.y += v1.y + xs.y + s.y;
        a.z += v1.z + xs.z + s.z;
        a.w += v1.w + xs.w + s.w;
        ((float4*)acc)[idx] = a;
    }
}

// ---------------------------------------------------------------------------
extern "C" void kernel_launch(void* const* d_in, const int* in_sizes, int n_in,
                              void* d_out, int out_size) {
    const int*   edge = (const int*)d_in[0];
    const float* uemb = (const float*)d_in[1];
    const float* iemb = (const float*)d_in[2];

    int E = in_sizes[0] / 2;       // total directed edges
    int Eh = E / 2;                // unique interactions (mirrored halves)
    int U = in_sizes[1] / EMB;
    int I = in_sizes[2] / EMB;
    int N = U + I;

    const int* row = edge;
    const int* col = edge + E;
    float* acc = (float*)d_out;

    uint2* h0; cudaGetSymbolAddress((void**)&h0, g_h0);
    uint2* h1; cudaGetSymbolAddress((void**)&h1, g_h1);
    uint2* h2; cudaGetSymbolAddress((void**)&h2, g_h2);

    int NB = (N + TB - 1) / TB;
    int EBh = (Eh + TB - 1) / TB;

    k_zero_deg  <<<NB, TB>>>(N);
    k_count_sym <<<EBh, TB>>>(row, col, Eh);
    k_scan_local<<<NB, TB>>>(N);
    k_scan_bsum <<<1, 1024>>>(NB);
    k_scan_add  <<<NB, TB>>>(N);
    k_fill_sym  <<<EBh, TB>>>(row, col, Eh);
    k_pad       <<<NB, TB>>>(N);

    int pblocks = (N * 16 + TB - 1) / TB;
    k_prep<<<pblocks, TB>>>(uemb, iemb, U, N);

    int lblocks = (N * 16 + TB - 1) / TB;        // half-warp per node
    k_layer<false><<<lblocks, TB>>>(h0, h1, uemb, iemb, U, acc, N);
    k_layer<false><<<lblocks, TB>>>(h1, h2, uemb, iemb, U, acc, N);
    k_layer<true ><<<lblocks, TB>>>(h2, nullptr, uemb, iemb, U, acc, N);
}

// round 10
// speedup vs baseline: 1.2241x; 1.1769x over previous
#include <cuda_runtime.h>
#include <cuda_fp16.h>
#include <cstdint>

#define EMB   64
#define NMAX  300000
#define EIMAX 2200000   // item-side adjacency (one entry per interaction)
#define TB    256

// ---------------- scratch (__device__ globals; allocation-free rule) --------
__device__ int   g_deg  [NMAX];
__device__ float g_dinv [NMAX];
__device__ int   g_loc  [NMAX];
__device__ int   g_bsum [2048];
__device__ int   g_bbase[2048];
__device__ int2  g_rng  [NMAX];               // users: {start,end} in col[]; items: {start,cursor} in g_adji
__device__ int2  g_adji [EIMAX];              // item rows: {user col, bits(dinv)}
__device__ uint2 g_h0[(size_t)NMAX * 16];     // x0 fp16
__device__ uint2 g_h1[(size_t)NMAX * 16];     // x1 fp16
__device__ uint2 g_h2[(size_t)NMAX * 16];     // x2 fp16

// ---------------------------------------------------------------------------
__device__ __forceinline__ float4 h4_to_f4(uint2 h) {
    __half2 a = *(__half2*)&h.x;
    __half2 b = *(__half2*)&h.y;
    float2 fa = __half22float2(a), fb = __half22float2(b);
    return make_float4(fa.x, fa.y, fb.x, fb.y);
}
__device__ __forceinline__ uint2 f4_to_h4(float4 v) {
    __half2 a = __floats2half2_rn(v.x, v.y);
    __half2 b = __floats2half2_rn(v.z, v.w);
    uint2 r;
    r.x = *(unsigned*)&a;
    r.y = *(unsigned*)&b;
    return r;
}

// ---------------------------------------------------------------------------
__global__ void k_zero_deg(int n) {
    int i = blockIdx.x * blockDim.x + threadIdx.x;
    if (i < n) g_deg[i] = 0;
}

__global__ void k_count_sym(const int* __restrict__ row,
                            const int* __restrict__ col, int Eh) {
    int i = blockIdx.x * blockDim.x + threadIdx.x;
    if (i >= Eh) return;
    atomicAdd(&g_deg[__ldcs(row + i)], 1);
    atomicAdd(&g_deg[__ldcs(col + i)], 1);
}

__global__ void k_scan_local(int n) {
    __shared__ int sh[TB];
    int i = blockIdx.x * TB + threadIdx.x;
    int v = (i < n) ? g_deg[i] : 0;
    sh[threadIdx.x] = v; __syncthreads();
    #pragma unroll
    for (int ofs = 1; ofs < TB; ofs <<= 1) {
        int t = (threadIdx.x >= ofs) ? sh[threadIdx.x - ofs] : 0;
        __syncthreads();
        sh[threadIdx.x] += t;
        __syncthreads();
    }
    if (i < n) g_loc[i] = sh[threadIdx.x] - v;
    if (threadIdx.x == TB - 1) g_bsum[blockIdx.x] = sh[TB - 1];
}

__global__ void k_scan_bsum(int nb) {
    __shared__ int sh[1024];
    int tid = threadIdx.x;
    int c0 = tid * 2, c1 = tid * 2 + 1;
    int a = (c0 < nb) ? g_bsum[c0] : 0;
    int b = (c1 < nb) ? g_bsum[c1] : 0;
    int tot = a + b;
    sh[tid] = tot; __syncthreads();
    #pragma unroll
    for (int ofs = 1; ofs < 1024; ofs <<= 1) {
        int t = (tid >= ofs) ? sh[tid - ofs] : 0;
        __syncthreads();
        sh[tid] += t;
        __syncthreads();
    }
    int base = sh[tid] - tot;
    if (c0 < nb) g_bbase[c0] = base;
    if (c1 < nb) g_bbase[c1] = base + a;
}

// users (i<U): row i's neighbors are col[o .. o+deg) in the INPUT col array
// items (i>=U): cursor into g_adji at o-Eh
__global__ void k_scan_add(int n, int U, int Eh) {
    int i = blockIdx.x * TB + threadIdx.x;
    if (i >= n) return;
    int o = g_loc[i] + g_bbase[blockIdx.x];
    int dg = g_deg[i];
    if (i < U) g_rng[i] = make_int2(o, o + dg);
    else       g_rng[i] = make_int2(o - Eh, o - Eh);
    g_dinv[i] = rsqrtf((float)(dg + 1));   // +1 self loop
}

// item rows only: 1 atomic + 1 store per interaction
__global__ void k_fill_item(const int* __restrict__ row,
                            const int* __restrict__ col, int Eh) {
    int i = blockIdx.x * blockDim.x + threadIdx.x;
    if (i >= Eh) return;
    int u = __ldcs(row + i);
    int v = __ldcs(col + i);
    float du = __ldg(&g_dinv[u]);
    int pv = atomicAdd(&g_rng[v].y, 1);
    g_adji[pv] = make_int2(u, __float_as_int(du));
}

// emb (fp32) -> x0 (fp16)
__global__ void k_prep(const float* __restrict__ ue,
                       const float* __restrict__ ie,
                       int U, int N) {
    int i = blockIdx.x * blockDim.x + threadIdx.x;
    int total = N * 16;
    if (i >= total) return;
    int node = i >> 4;
    int c = i & 15;
    const float4* p = (node < U)
        ? (const float4*)ue + (size_t)node * 16
        : (const float4*)ie + (size_t)(node - U) * 16;
    g_h0[i] = f4_to_h4(__ldcs(p + c));
}

// ---------------------------------------------------------------------------
// Fused layer: 16 threads per node (half-warp), thread c owns halves [4c,4c+4).
// User nodes read neighbor cols from the input col array (weight = d*dinv[c]).
// Item nodes read {col, weight} from g_adji.
template<bool LAST>
__global__ void __launch_bounds__(TB)
k_layer(const uint2* __restrict__ x,
        uint2* __restrict__ xn,
        const int* __restrict__ gcol,        // input col array (items per user edge)
        const float* __restrict__ ue,
        const float* __restrict__ ie,
        int U,
        float* __restrict__ acc,
        int N) {
    int t = blockIdx.x * blockDim.x + threadIdx.x;
    int node = t >> 4;
    if (node >= N) return;
    int c = t & 15;

    float d = __ldg(&g_dinv[node]);
    int2 rng = __ldg(&g_rng[node]);
    int e = rng.x, end = rng.y;

    size_t idx = (size_t)node * 16 + c;
    float4 xs = h4_to_f4(__ldg(x + idx));
    float sw = d * d;
    float4 s0 = make_float4(sw * xs.x, sw * xs.y, sw * xs.z, sw * xs.w);
    float4 s1 = make_float4(0.f, 0.f, 0.f, 0.f);

    if (node < U) {
        // ---- user rows: adjacency = input col stream, weight via dinv table
        while (e + 4 <= end) {
            int c0 = __ldcs(gcol + e);
            int c1 = __ldcs(gcol + e + 1);
            int c2 = __ldcs(gcol + e + 2);
            int c3 = __ldcs(gcol + e + 3);
            float4 v0 = h4_to_f4(__ldg(x + (size_t)c0 * 16 + c));
            float4 v1 = h4_to_f4(__ldg(x + (size_t)c1 * 16 + c));
            float4 v2 = h4_to_f4(__ldg(x + (size_t)c2 * 16 + c));
            float4 v3 = h4_to_f4(__ldg(x + (size_t)c3 * 16 + c));
            float w0 = d * __ldg(&g_dinv[c0]);
            float w1 = d * __ldg(&g_dinv[c1]);
            float w2 = d * __ldg(&g_dinv[c2]);
            float w3 = d * __ldg(&g_dinv[c3]);
            s0.x += w0 * v0.x + w2 * v2.x;  s1.x += w1 * v1.x + w3 * v3.x;
            s0.y += w0 * v0.y + w2 * v2.y;  s1.y += w1 * v1.y + w3 * v3.y;
            s0.z += w0 * v0.z + w2 * v2.z;  s1.z += w1 * v1.z + w3 * v3.z;
            s0.w += w0 * v0.w + w2 * v2.w;  s1.w += w1 * v1.w + w3 * v3.w;
            e += 4;
        }
        if (e + 2 <= end) {
            int c0 = __ldcs(gcol + e);
            int c1 = __ldcs(gcol + e + 1);
            float4 v0 = h4_to_f4(__ldg(x + (size_t)c0 * 16 + c));
            float4 v1 = h4_to_f4(__ldg(x + (size_t)c1 * 16 + c));
            float w0 = d * __ldg(&g_dinv[c0]);
            float w1 = d * __ldg(&g_dinv[c1]);
            s0.x += w0 * v0.x; s0.y += w0 * v0.y; s0.z += w0 * v0.z; s0.w += w0 * v0.w;
            s1.x += w1 * v1.x; s1.y += w1 * v1.y; s1.z += w1 * v1.z; s1.w += w1 * v1.w;
            e += 2;
        }
        if (e < end) {
            int c0 = __ldcs(gcol + e);
            float4 v0 = h4_to_f4(__ldg(x + (size_t)c0 * 16 + c));
            float w0 = d * __ldg(&g_dinv[c0]);
            s0.x += w0 * v0.x; s0.y += w0 * v0.y; s0.z += w0 * v0.z; s0.w += w0 * v0.w;
        }
    } else {
        // ---- item rows: {col, weight} inline
        while (e + 4 <= end) {
            int2 a0 = __ldcs(&g_adji[e]);
            int2 a1 = __ldcs(&g_adji[e + 1]);
            int2 a2 = __ldcs(&g_adji[e + 2]);
            int2 a3 = __ldcs(&g_adji[e + 3]);
            float4 v0 = h4_to_f4(__ldg(x + (size_t)a0.x * 16 + c));
            float4 v1 = h4_to_f4(__ldg(x + (size_t)a1.x * 16 + c));
            float4 v2 = h4_to_f4(__ldg(x + (size_t)a2.x * 16 + c));
            float4 v3 = h4_to_f4(__ldg(x + (size_t)a3.x * 16 + c));
            float w0 = d * __int_as_float(a0.y);
            float w1 = d * __int_as_float(a1.y);
            float w2 = d * __int_as_float(a2.y);
            float w3 = d * __int_as_float(a3.y);
            s0.x += w0 * v0.x + w2 * v2.x;  s1.x += w1 * v1.x + w3 * v3.x;
            s0.y += w0 * v0.y + w2 * v2.y;  s1.y += w1 * v1.y + w3 * v3.y;
            s0.z += w0 * v0.z + w2 * v2.z;  s1.z += w1 * v1.z + w3 * v3.z;
            s0.w += w0 * v0.w + w2 * v2.w;  s1.w += w1 * v1.w + w3 * v3.w;
            e += 4;
        }
        if (e + 2 <= end) {
            int2 a0 = __ldcs(&g_adji[e]);
            int2 a1 = __ldcs(&g_adji[e + 1]);
            float4 v0 = h4_to_f4(__ldg(x + (size_t)a0.x * 16 + c));
            float4 v1 = h4_to_f4(__ldg(x + (size_t)a1.x * 16 + c));
            float w0 = d * __int_as_float(a0.y);
            float w1 = d * __int_as_float(a1.y);
            s0.x += w0 * v0.x; s0.y += w0 * v0.y; s0.z += w0 * v0.z; s0.w += w0 * v0.w;
            s1.x += w1 * v1.x; s1.y += w1 * v1.y; s1.z += w1 * v1.z; s1.w += w1 * v1.w;
            e += 2;
        }
        if (e < end) {
            int2 a0 = __ldcs(&g_adji[e]);
            float4 v0 = h4_to_f4(__ldg(x + (size_t)a0.x * 16 + c));
            float w0 = d * __int_as_float(a0.y);
            s0.x += w0 * v0.x; s0.y += w0 * v0.y; s0.z += w0 * v0.z; s0.w += w0 * v0.w;
        }
    }
    float4 s = make_float4(s0.x + s1.x, s0.y + s1.y, s0.z + s1.z, s0.w + s1.w);

    if (!LAST) {
        xn[idx] = f4_to_h4(s);
    } else {
        const float4* pe = (node < U)
            ? (const float4*)ue + (size_t)node * 16
            : (const float4*)ie + (size_t)(node - U) * 16;
        float4 a  = __ldcs(pe + c);
        float4 v1 = h4_to_f4(__ldcs(&g_h1[idx]));
        a.x += v1.x + xs.x + s.x;
        a.y += v1.y + xs.y + s.y;
        a.z += v1.z + xs.z + s.z;
        a.w += v1.w + xs.w + s.w;
        __stcs((float4*)acc + idx, a);
    }
}

// ---------------------------------------------------------------------------
extern "C" void kernel_launch(void* const* d_in, const int* in_sizes, int n_in,
                              void* d_out, int out_size) {
    const int*   edge = (const int*)d_in[0];
    const float* uemb = (const float*)d_in[1];
    const float* iemb = (const float*)d_in[2];

    int E = in_sizes[0] / 2;       // total directed edges
    int Eh = E / 2;                // unique interactions (mirrored halves)
    int U = in_sizes[1] / EMB;
    int I = in_sizes[2] / EMB;
    int N = U + I;

    const int* row = edge;         // first Eh: user ids (sorted ascending)
    const int* col = edge + E;     // first Eh: item ids (grouped per user)
    float* acc = (float*)d_out;

    uint2* h0; cudaGetSymbolAddress((void**)&h0, g_h0);
    uint2* h1; cudaGetSymbolAddress((void**)&h1, g_h1);
    uint2* h2; cudaGetSymbolAddress((void**)&h2, g_h2);

    int NB = (N + TB - 1) / TB;
    int EBh = (Eh + TB - 1) / TB;

    k_zero_deg  <<<NB, TB>>>(N);
    k_count_sym <<<EBh, TB>>>(row, col, Eh);
    k_scan_local<<<NB, TB>>>(N);
    k_scan_bsum <<<1, 1024>>>(NB);
    k_scan_add  <<<NB, TB>>>(N, U, Eh);
    k_fill_item <<<EBh, TB>>>(row, col, Eh);

    int pblocks = (N * 16 + TB - 1) / TB;
    k_prep<<<pblocks, TB>>>(uemb, iemb, U, N);

    int lblocks = (N * 16 + TB - 1) / TB;        // half-warp per node
    k_layer<false><<<lblocks, TB>>>(h0, h1, col, uemb, iemb, U, acc, N);
    k_layer<false><<<lblocks, TB>>>(h1, h2, col, uemb, iemb, U, acc, N);
    k_layer<true ><<<lblocks, TB>>>(h2, nullptr, col, uemb, iemb, U, acc, N);
}

// round 11
// speedup vs baseline: 1.2857x; 1.0503x over previous
#include <cuda_runtime.h>
#include <cuda_fp16.h>
#include <cstdint>

#define EMB   64
#define NMAX  300000
#define EIMAX 2200000   // item-side adjacency (one entry per interaction)
#define TB    256

// ---------------- scratch (__device__ globals; allocation-free rule) --------
__device__ int   g_deg  [NMAX];
__device__ float g_dinv [NMAX];
__device__ int   g_loc  [NMAX];
__device__ int   g_bsum [2048];
__device__ int   g_bbase[2048];
__device__ int2  g_rng  [NMAX];               // users: {start,end} in col[]; items: {start,cursor} in g_adji
__device__ int2  g_adji [EIMAX];              // item rows: {user col, bits(dinv)}
__device__ uint2 g_h0[(size_t)NMAX * 16];     // x0 fp16
__device__ uint2 g_h1[(size_t)NMAX * 16];     // x1 fp16
__device__ uint2 g_h2[(size_t)NMAX * 16];     // x2 fp16

// ---------------------------------------------------------------------------
__device__ __forceinline__ float4 h4_to_f4(uint2 h) {
    __half2 a = *(__half2*)&h.x;
    __half2 b = *(__half2*)&h.y;
    float2 fa = __half22float2(a), fb = __half22float2(b);
    return make_float4(fa.x, fa.y, fb.x, fb.y);
}
__device__ __forceinline__ uint2 f4_to_h4(float4 v) {
    __half2 a = __floats2half2_rn(v.x, v.y);
    __half2 b = __floats2half2_rn(v.z, v.w);
    uint2 r;
    r.x = *(unsigned*)&a;
    r.y = *(unsigned*)&b;
    return r;
}

// ---------------------------------------------------------------------------
__global__ void k_zero_deg(int n) {
    int i = blockIdx.x * blockDim.x + threadIdx.x;
    if (i < n) g_deg[i] = 0;
}

__global__ void k_count_sym(const int* __restrict__ row,
                            const int* __restrict__ col, int Eh) {
    int i = blockIdx.x * blockDim.x + threadIdx.x;
    if (i >= Eh) return;
    atomicAdd(&g_deg[__ldg(row + i)], 1);
    atomicAdd(&g_deg[__ldg(col + i)], 1);
}

__global__ void k_scan_local(int n) {
    __shared__ int sh[TB];
    int i = blockIdx.x * TB + threadIdx.x;
    int v = (i < n) ? g_deg[i] : 0;
    sh[threadIdx.x] = v; __syncthreads();
    #pragma unroll
    for (int ofs = 1; ofs < TB; ofs <<= 1) {
        int t = (threadIdx.x >= ofs) ? sh[threadIdx.x - ofs] : 0;
        __syncthreads();
        sh[threadIdx.x] += t;
        __syncthreads();
    }
    if (i < n) g_loc[i] = sh[threadIdx.x] - v;
    if (threadIdx.x == TB - 1) g_bsum[blockIdx.x] = sh[TB - 1];
}

__global__ void k_scan_bsum(int nb) {
    __shared__ int sh[1024];
    int tid = threadIdx.x;
    int c0 = tid * 2, c1 = tid * 2 + 1;
    int a = (c0 < nb) ? g_bsum[c0] : 0;
    int b = (c1 < nb) ? g_bsum[c1] : 0;
    int tot = a + b;
    sh[tid] = tot; __syncthreads();
    #pragma unroll
    for (int ofs = 1; ofs < 1024; ofs <<= 1) {
        int t = (tid >= ofs) ? sh[tid - ofs] : 0;
        __syncthreads();
        sh[tid] += t;
        __syncthreads();
    }
    int base = sh[tid] - tot;
    if (c0 < nb) g_bbase[c0] = base;
    if (c1 < nb) g_bbase[c1] = base + a;
}

// users (i<U): row i's neighbors are col[o .. o+deg) in the INPUT col array
// items (i>=U): cursor into g_adji at o-Eh
__global__ void k_scan_add(int n, int U, int Eh) {
    int i = blockIdx.x * TB + threadIdx.x;
    if (i >= n) return;
    int o = g_loc[i] + g_bbase[blockIdx.x];
    int dg = g_deg[i];
    if (i < U) g_rng[i] = make_int2(o, o + dg);
    else       g_rng[i] = make_int2(o - Eh, o - Eh);
    g_dinv[i] = rsqrtf((float)(dg + 1));   // +1 self loop
}

// item rows only: 1 atomic + 1 store per interaction
__global__ void k_fill_item(const int* __restrict__ row,
                            const int* __restrict__ col, int Eh) {
    int i = blockIdx.x * blockDim.x + threadIdx.x;
    if (i >= Eh) return;
    int u = __ldg(row + i);
    int v = __ldg(col + i);
    float du = __ldg(&g_dinv[u]);
    int pv = atomicAdd(&g_rng[v].y, 1);
    g_adji[pv] = make_int2(u, __float_as_int(du));
}

// emb (fp32) -> x0 (fp16)
__global__ void k_prep(const float* __restrict__ ue,
                       const float* __restrict__ ie,
                       int U, int N) {
    int i = blockIdx.x * blockDim.x + threadIdx.x;
    int total = N * 16;
    if (i >= total) return;
    int node = i >> 4;
    int c = i & 15;
    const float4* p = (node < U)
        ? (const float4*)ue + (size_t)node * 16
        : (const float4*)ie + (size_t)(node - U) * 16;
    g_h0[i] = f4_to_h4(__ldg(p + c));
}

// ---------------------------------------------------------------------------
// Fused layer: 16 threads per node (half-warp), thread c owns halves [4c,4c+4).
// User nodes read neighbor cols from the input col array (weight = d*dinv[c]).
// Item nodes read {col, weight} from g_adji.
template<bool LAST>
__global__ void __launch_bounds__(TB)
k_layer(const uint2* __restrict__ x,
        uint2* __restrict__ xn,
        const int* __restrict__ gcol,        // input col array (items per user edge)
        const float* __restrict__ ue,
        const float* __restrict__ ie,
        int U,
        float* __restrict__ acc,
        int N) {
    int t = blockIdx.x * blockDim.x + threadIdx.x;
    int node = t >> 4;
    if (node >= N) return;
    int c = t & 15;

    float d = __ldg(&g_dinv[node]);
    int2 rng = __ldg(&g_rng[node]);
    int e = rng.x, end = rng.y;

    size_t idx = (size_t)node * 16 + c;
    float4 xs = h4_to_f4(__ldg(x + idx));
    float sw = d * d;
    float4 s0 = make_float4(sw * xs.x, sw * xs.y, sw * xs.z, sw * xs.w);
    float4 s1 = make_float4(0.f, 0.f, 0.f, 0.f);

    if (node < U) {
        // ---- user rows: adjacency = input col stream, weight via dinv table
        while (e + 4 <= end) {
            int c0 = __ldg(gcol + e);
            int c1 = __ldg(gcol + e + 1);
            int c2 = __ldg(gcol + e + 2);
            int c3 = __ldg(gcol + e + 3);
            float4 v0 = h4_to_f4(__ldg(x + (size_t)c0 * 16 + c));
            float4 v1 = h4_to_f4(__ldg(x + (size_t)c1 * 16 + c));
            float4 v2 = h4_to_f4(__ldg(x + (size_t)c2 * 16 + c));
            float4 v3 = h4_to_f4(__ldg(x + (size_t)c3 * 16 + c));
            float w0 = d * __ldg(&g_dinv[c0]);
            float w1 = d * __ldg(&g_dinv[c1]);
            float w2 = d * __ldg(&g_dinv[c2]);
            float w3 = d * __ldg(&g_dinv[c3]);
            s0.x += w0 * v0.x + w2 * v2.x;  s1.x += w1 * v1.x + w3 * v3.x;
            s0.y += w0 * v0.y + w2 * v2.y;  s1.y += w1 * v1.y + w3 * v3.y;
            s0.z += w0 * v0.z + w2 * v2.z;  s1.z += w1 * v1.z + w3 * v3.z;
            s0.w += w0 * v0.w + w2 * v2.w;  s1.w += w1 * v1.w + w3 * v3.w;
            e += 4;
        }
        if (e + 2 <= end) {
            int c0 = __ldg(gcol + e);
            int c1 = __ldg(gcol + e + 1);
            float4 v0 = h4_to_f4(__ldg(x + (size_t)c0 * 16 + c));
            float4 v1 = h4_to_f4(__ldg(x + (size_t)c1 * 16 + c));
            float w0 = d * __ldg(&g_dinv[c0]);
            float w1 = d * __ldg(&g_dinv[c1]);
            s0.x += w0 * v0.x; s0.y += w0 * v0.y; s0.z += w0 * v0.z; s0.w += w0 * v0.w;
            s1.x += w1 * v1.x; s1.y += w1 * v1.y; s1.z += w1 * v1.z; s1.w += w1 * v1.w;
            e += 2;
        }
        if (e < end) {
            int c0 = __ldg(gcol + e);
            float4 v0 = h4_to_f4(__ldg(x + (size_t)c0 * 16 + c));
            float w0 = d * __ldg(&g_dinv[c0]);
            s0.x += w0 * v0.x; s0.y += w0 * v0.y; s0.z += w0 * v0.z; s0.w += w0 * v0.w;
        }
    } else {
        // ---- item rows: {col, weight} inline
        while (e + 4 <= end) {
            int2 a0 = __ldg(&g_adji[e]);
            int2 a1 = __ldg(&g_adji[e + 1]);
            int2 a2 = __ldg(&g_adji[e + 2]);
            int2 a3 = __ldg(&g_adji[e + 3]);
            float4 v0 = h4_to_f4(__ldg(x + (size_t)a0.x * 16 + c));
            float4 v1 = h4_to_f4(__ldg(x + (size_t)a1.x * 16 + c));
            float4 v2 = h4_to_f4(__ldg(x + (size_t)a2.x * 16 + c));
            float4 v3 = h4_to_f4(__ldg(x + (size_t)a3.x * 16 + c));
            float w0 = d * __int_as_float(a0.y);
            float w1 = d * __int_as_float(a1.y);
            float w2 = d * __int_as_float(a2.y);
            float w3 = d * __int_as_float(a3.y);
            s0.x += w0 * v0.x + w2 * v2.x;  s1.x += w1 * v1.x + w3 * v3.x;
            s0.y += w0 * v0.y + w2 * v2.y;  s1.y += w1 * v1.y + w3 * v3.y;
            s0.z += w0 * v0.z + w2 * v2.z;  s1.z += w1 * v1.z + w3 * v3.z;
            s0.w += w0 * v0.w + w2 * v2.w;  s1.w += w1 * v1.w + w3 * v3.w;
            e += 4;
        }
        if (e + 2 <= end) {
            int2 a0 = __ldg(&g_adji[e]);
            int2 a1 = __ldg(&g_adji[e + 1]);
            float4 v0 = h4_to_f4(__ldg(x + (size_t)a0.x * 16 + c));
            float4 v1 = h4_to_f4(__ldg(x + (size_t)a1.x * 16 + c));
            float w0 = d * __int_as_float(a0.y);
            float w1 = d * __int_as_float(a1.y);
            s0.x += w0 * v0.x; s0.y += w0 * v0.y; s0.z += w0 * v0.z; s0.w += w0 * v0.w;
            s1.x += w1 * v1.x; s1.y += w1 * v1.y; s1.z += w1 * v1.z; s1.w += w1 * v1.w;
            e += 2;
        }
        if (e < end) {
            int2 a0 = __ldg(&g_adji[e]);
            float4 v0 = h4_to_f4(__ldg(x + (size_t)a0.x * 16 + c));
            float w0 = d * __int_as_float(a0.y);
            s0.x += w0 * v0.x; s0.y += w0 * v0.y; s0.z += w0 * v0.z; s0.w += w0 * v0.w;
        }
    }
    float4 s = make_float4(s0.x + s1.x, s0.y + s1.y, s0.z + s1.z, s0.w + s1.w);

    if (!LAST) {
        xn[idx] = f4_to_h4(s);
    } else {
        const float4* pe = (node < U)
            ? (const float4*)ue + (size_t)node * 16
            : (const float4*)ie + (size_t)(node - U) * 16;
        float4 a  = __ldg(pe + c);
        float4 v1 = h4_to_f4(__ldg(&g_h1[idx]));
        a.x += v1.x + xs.x + s.x;
        a.y += v1.y + xs.y + s.y;
        a.z += v1.z + xs.z + s.z;
        a.w += v1.w + xs.w + s.w;
        __stcs((float4*)acc + idx, a);   // write-once output: evict-first
    }
}

// ---------------------------------------------------------------------------
extern "C" void kernel_launch(void* const* d_in, const int* in_sizes, int n_in,
                              void* d_out, int out_size) {
    const int*   edge = (const int*)d_in[0];
    const float* uemb = (const float*)d_in[1];
    const float* iemb = (const float*)d_in[2];

    int E = in_sizes[0] / 2;       // total directed edges
    int Eh = E / 2;                // unique interactions (mirrored halves)
    int U = in_sizes[1] / EMB;
    int I = in_sizes[2] / EMB;
    int N = U + I;

    const int* row = edge;         // first Eh: user ids (sorted ascending)
    const int* col = edge + E;     // first Eh: item ids (grouped per user)
    float* acc = (float*)d_out;

    uint2* h0; cudaGetSymbolAddress((void**)&h0, g_h0);
    uint2* h1; cudaGetSymbolAddress((void**)&h1, g_h1);
    uint2* h2; cudaGetSymbolAddress((void**)&h2, g_h2);

    int NB = (N + TB - 1) / TB;
    int EBh = (Eh + TB - 1) / TB;

    k_zero_deg  <<<NB, TB>>>(N);
    k_count_sym <<<EBh, TB>>>(row, col, Eh);
    k_scan_local<<<NB, TB>>>(N);
    k_scan_bsum <<<1, 1024>>>(NB);
    k_scan_add  <<<NB, TB>>>(N, U, Eh);
    k_fill_item <<<EBh, TB>>>(row, col, Eh);

    int pblocks = (N * 16 + TB - 1) / TB;
    k_prep<<<pblocks, TB>>>(uemb, iemb, U, N);

    int lblocks = (N * 16 + TB - 1) / TB;        // half-warp per node
    k_layer<false><<<lblocks, TB>>>(h0, h1, col, uemb, iemb, U, acc, N);
    k_layer<false><<<lblocks, TB>>>(h1, h2, col, uemb, iemb, U, acc, N);
    k_layer<true ><<<lblocks, TB>>>(h2, nullptr, col, uemb, iemb, U, acc, N);
}